// round 1
// baseline (speedup 1.0000x reference)
#include <cuda_runtime.h>
#include <cuda_bf16.h>
#include <math.h>

// Problem constants
#define BB 2
#define TT 2048
#define DD 1024
#define HH 16
#define HD 64
#define WW 16
#define EE 8
#define MM (BB*TT)           // 4096
typedef unsigned long long u64;

// ---------------- scratch (device globals; no allocation allowed) ----------------
__device__ float g_xt[(size_t)BB*DD*TT];     // x transposed (B, D, T)
__device__ float g_q [(size_t)BB*TT*DD];
__device__ float g_k [(size_t)BB*TT*DD];
__device__ float g_v [(size_t)BB*TT*DD];
__device__ float g_ao[(size_t)BB*TT*DD];     // attention output, (B,T,D)
__device__ float g_alpha[(size_t)BB*HH*EE*TT];

__device__ __forceinline__ float2 unpack2(u64 u) {
    float2 r;
    r.x = __uint_as_float((unsigned)(u & 0xffffffffu));
    r.y = __uint_as_float((unsigned)(u >> 32));
    return r;
}

// ---------------- 1) transpose x (B,T,D) -> xt (B,D,T) ----------------
__global__ void transpose_kernel(const float* __restrict__ x) {
    __shared__ float tile[32][33];
    int b  = blockIdx.z;
    int t0 = blockIdx.x * 32, d0 = blockIdx.y * 32;
    int tx = threadIdx.x, ty = threadIdx.y;   // block (32, 8)
    #pragma unroll
    for (int j = 0; j < 32; j += 8)
        tile[ty + j][tx] = x[((size_t)b*TT + t0 + ty + j)*DD + d0 + tx];
    __syncthreads();
    #pragma unroll
    for (int j = 0; j < 32; j += 8)
        g_xt[((size_t)b*DD + d0 + ty + j)*TT + t0 + tx] = tile[tx][ty + j];
}

// ---------------- 2) causal conv as implicit GEMM ----------------
// out[b,t,o] = sum_{i,w} x[b, t+w-15, i] * wgt[o,i,w] + bias[o]
// Block tile: 128 t  x 128 o. Per channel i: 143 x-floats (sliding window) + 128x16 weights.
// f32x2 packed accumulators: pairs over adjacent o. x stored duplicated (v,v) for LDS.64,
// weights stored [w][chunk-of-8 per tx, padded to 10] -> conflict-free LDS.64.
__global__ __launch_bounds__(256)
void conv_kernel(const float* __restrict__ wgt, const float* __restrict__ bias,
                 float* __restrict__ out) {
    __shared__ float xs[286];          // 143 duplicated pairs
    __shared__ float ws[16*160];       // [w][(o/8)*10 + o%8]

    const int tid = threadIdx.x;
    const int m0 = blockIdx.x * 128;
    const int b  = m0 >> 11;           // / 2048
    const int t0 = m0 & 2047;
    const int o0 = blockIdx.y * 128;
    const int tx = tid & 15, ty = tid >> 4;

    // loaders
    const int o_l = tid >> 1;              // 0..127
    const int wq  = (tid & 1) * 8;         // 0 or 8
    const float* wbase = wgt + (size_t)(o0 + o_l)*(DD*WW) + wq;
    const int wdst = (o_l >> 3)*10 + (o_l & 7);
    const int xt_t = t0 - 15 + tid;
    const float* xbase = g_xt + (size_t)b*DD*TT;
    const bool xok = (tid < 143) && (xt_t >= 0);

    float4 wr0 = *(const float4*)(wbase);
    float4 wr1 = *(const float4*)(wbase + 4);
    float  xr  = xok ? xbase[xt_t] : 0.f;

    u64 acc[8][4];
    #pragma unroll
    for (int a = 0; a < 8; a++)
        #pragma unroll
        for (int c = 0; c < 4; c++) acc[a][c] = 0ull;

    for (int i = 0; i < DD; ++i) {
        __syncthreads();
        #pragma unroll
        for (int j = 0; j < 4; ++j) ws[(wq + j)*160 + wdst]     = ((const float*)&wr0)[j];
        #pragma unroll
        for (int j = 0; j < 4; ++j) ws[(wq + 4 + j)*160 + wdst] = ((const float*)&wr1)[j];
        if (tid < 143) *(float2*)(xs + tid*2) = make_float2(xr, xr);
        __syncthreads();
        if (i + 1 < DD) {
            const float* wp = wbase + (size_t)(i + 1)*WW;
            wr0 = *(const float4*)wp;
            wr1 = *(const float4*)(wp + 4);
            xr = xok ? xbase[(size_t)(i + 1)*TT + xt_t] : 0.f;
        }
        #pragma unroll
        for (int half = 0; half < 2; ++half) {
            u64 xr2[15];
            #pragma unroll
            for (int j = 0; j < 15; ++j)
                xr2[j] = *(const u64*)(xs + 2*(ty*8 + half*8 + j));
            #pragma unroll
            for (int w = 0; w < 8; ++w) {
                u64 b2[4];
                const u64* wp2 = (const u64*)(ws + (half*8 + w)*160 + tx*10);
                #pragma unroll
                for (int tn = 0; tn < 4; ++tn) b2[tn] = wp2[tn];
                #pragma unroll
                for (int tm = 0; tm < 8; ++tm) {
                    #pragma unroll
                    for (int tn = 0; tn < 4; ++tn)
                        asm("fma.rn.f32x2 %0, %1, %2, %0;"
                            : "+l"(acc[tm][tn]) : "l"(xr2[tm + w]), "l"(b2[tn]));
                }
            }
        }
    }
    // epilogue
    #pragma unroll
    for (int tm = 0; tm < 8; ++tm) {
        int t = t0 + ty*8 + tm;
        float* orow = out + ((size_t)b*TT + t)*DD + o0 + tx*8;
        #pragma unroll
        for (int tn = 0; tn < 4; ++tn) {
            float2 v = unpack2(acc[tm][tn]);
            int oc = o0 + tx*8 + tn*2;
            orow[tn*2]     = v.x + bias[oc];
            orow[tn*2 + 1] = v.y + bias[oc + 1];
        }
    }
}

// ---------------- 3) SGEMM: C[m,n] = sum_k A[m,k]*Bw[n,k] + bias[n] ----------------
// N = 1024 fixed. BM=BN=128, BK=16, 256 threads, 8x8 per thread, f32x2 packed over n.
__global__ __launch_bounds__(256)
void sgemm_kernel(const float* __restrict__ A, const float* __restrict__ Bw,
                  const float* __restrict__ bias, float* __restrict__ C, int K) {
    __shared__ float Asd[16*256];   // duplicated pairs: [k][m*2 (+0/1)]
    __shared__ float Bst[16*160];   // [k][(n/8)*10 + n%8]
    const int tid = threadIdx.x;
    const int m0 = blockIdx.x * 128, n0 = blockIdx.y * 128;
    const int tx = tid & 15, ty = tid >> 4;
    const int row = tid >> 1, half = (tid & 1) * 8;
    const float* Ap = A  + (size_t)(m0 + row)*K + half;
    const float* Bp = Bw + (size_t)(n0 + row)*K + half;
    const int ndst = (row >> 3)*10 + (row & 7);

    u64 acc[8][4];
    #pragma unroll
    for (int a = 0; a < 8; a++)
        #pragma unroll
        for (int c = 0; c < 4; c++) acc[a][c] = 0ull;

    float4 ar0 = *(const float4*)Ap,       ar1 = *(const float4*)(Ap + 4);
    float4 br0 = *(const float4*)Bp,       br1 = *(const float4*)(Bp + 4);

    for (int k0 = 0; k0 < K; k0 += 16) {
        __syncthreads();
        #pragma unroll
        for (int j = 0; j < 4; ++j) {
            float va = ((const float*)&ar0)[j];
            *(float2*)(Asd + (half + j)*256 + row*2) = make_float2(va, va);
            Bst[(half + j)*160 + ndst] = ((const float*)&br0)[j];
        }
        #pragma unroll
        for (int j = 0; j < 4; ++j) {
            float va = ((const float*)&ar1)[j];
            *(float2*)(Asd + (half + 4 + j)*256 + row*2) = make_float2(va, va);
            Bst[(half + 4 + j)*160 + ndst] = ((const float*)&br1)[j];
        }
        __syncthreads();
        if (k0 + 16 < K) {
            ar0 = *(const float4*)(Ap + k0 + 16); ar1 = *(const float4*)(Ap + k0 + 20);
            br0 = *(const float4*)(Bp + k0 + 16); br1 = *(const float4*)(Bp + k0 + 20);
        }
        #pragma unroll
        for (int k = 0; k < 16; ++k) {
            u64 a2[8], b2[4];
            const u64* ap2 = (const u64*)(Asd + k*256 + ty*16);
            const u64* bp2 = (const u64*)(Bst + k*160 + tx*10);
            #pragma unroll
            for (int tn = 0; tn < 4; ++tn) b2[tn] = bp2[tn];
            #pragma unroll
            for (int tm = 0; tm < 8; ++tm) a2[tm] = ap2[tm];
            #pragma unroll
            for (int tm = 0; tm < 8; ++tm)
                #pragma unroll
                for (int tn = 0; tn < 4; ++tn)
                    asm("fma.rn.f32x2 %0, %1, %2, %0;"
                        : "+l"(acc[tm][tn]) : "l"(a2[tm]), "l"(b2[tn]));
        }
    }
    #pragma unroll
    for (int tm = 0; tm < 8; ++tm) {
        float* crow = C + (size_t)(m0 + ty*8 + tm)*DD + n0 + tx*8;
        #pragma unroll
        for (int tn = 0; tn < 4; ++tn) {
            float2 v = unpack2(acc[tm][tn]);
            int nc = n0 + tx*8 + tn*2;
            crow[tn*2]     = v.x + bias[nc];
            crow[tn*2 + 1] = v.y + bias[nc + 1];
        }
    }
}

// ---------------- 4) log-sparse global softmax alpha[b,h,e,t] ----------------
__global__ void alpha_kernel() {
    const int idx = blockIdx.x;                 // (b*H + h)*E + e
    const int e = idx & 7;
    const int h = (idx >> 3) & 15;
    const int b = idx >> 7;
    const int sh = 1 << e;
    const float* qb = g_q + (size_t)b*TT*DD + h*HD;
    const float* kb = g_k + (size_t)b*TT*DD + h*HD;
    const int tid = threadIdx.x;                // 256 threads, 8 t's each

    float s[8];
    float mx = -1e30f;
    #pragma unroll
    for (int j = 0; j < 8; ++j) {
        int t  = tid + j*256;
        int tk = (t + sh) & (TT - 1);
        const float4* qp = (const float4*)(qb + (size_t)t *DD);
        const float4* kp = (const float4*)(kb + (size_t)tk*DD);
        float a = 0.f;
        #pragma unroll
        for (int d = 0; d < 16; ++d) {
            float4 x = qp[d], y = kp[d];
            a += x.x*y.x + x.y*y.y + x.z*y.z + x.w*y.w;
        }
        s[j] = a * 0.125f;                      // 1/sqrt(64)
        mx = fmaxf(mx, s[j]);
    }
    __shared__ float red[256];
    red[tid] = mx; __syncthreads();
    for (int st = 128; st > 0; st >>= 1) {
        if (tid < st) red[tid] = fmaxf(red[tid], red[tid + st]);
        __syncthreads();
    }
    mx = red[0]; __syncthreads();
    float sum = 0.f;
    #pragma unroll
    for (int j = 0; j < 8; ++j) { s[j] = expf(s[j] - mx); sum += s[j]; }
    red[tid] = sum; __syncthreads();
    for (int st = 128; st > 0; st >>= 1) {
        if (tid < st) red[tid] += red[tid + st];
        __syncthreads();
    }
    const float inv = 1.f / red[0];
    float* ab = g_alpha + (size_t)idx * TT;
    #pragma unroll
    for (int j = 0; j < 8; ++j) ab[tid + j*256] = s[j] * inv;
}

// ---------------- 5) local window attention + log-sparse combine ----------------
// One block per (b,t); 4 warps loop over 16 heads. Writes g_ao (B,T,D).
__global__ void combine_kernel() {
    const int t = blockIdx.x, b = blockIdx.y;
    const int warp = threadIdx.x >> 5, lane = threadIdx.x & 31;
    const size_t base = (size_t)b*TT*DD;

    for (int h = warp; h < HH; h += 4) {
        const float* qp = g_q + base + (size_t)t*DD + h*HD;
        float sc = 0.f;
        if (lane < 16) {
            int tk = t - 15 + lane;
            if (tk >= 0) {
                const float4* q4 = (const float4*)qp;
                const float4* k4 = (const float4*)(g_k + base + (size_t)tk*DD + h*HD);
                float a = 0.f;
                #pragma unroll
                for (int d = 0; d < 16; ++d) {
                    float4 x = q4[d], y = k4[d];
                    a += x.x*y.x + x.y*y.y + x.z*y.z + x.w*y.w;
                }
                sc = a * 0.125f;
            }
            // tk < 0: padded key is zero vector -> score exactly 0 (matches reference)
        }
        float m = sc;
        #pragma unroll
        for (int o = 8; o; o >>= 1) m = fmaxf(m, __shfl_xor_sync(0xffffffffu, m, o, 16));
        float p = expf(sc - m);
        float ss = p;
        #pragma unroll
        for (int o = 8; o; o >>= 1) ss += __shfl_xor_sync(0xffffffffu, ss, o, 16);
        float pn = p / ss;                      // valid in lanes 0..15

        const int d0 = lane * 2;
        float o0 = 0.f, o1 = 0.f;
        #pragma unroll
        for (int j = 0; j < 16; ++j) {
            float pj = __shfl_sync(0xffffffffu, pn, j);
            int tk = t - 15 + j;
            if (tk >= 0) {
                float2 v = *(const float2*)(g_v + base + (size_t)tk*DD + h*HD + d0);
                o0 += pj * v.x; o1 += pj * v.y;
            }
        }
        const float* ab = g_alpha + (size_t)(b*HH + h)*EE*TT;
        #pragma unroll
        for (int e = 0; e < EE; ++e) {
            float a = ab[(size_t)e*TT + t];
            int tv = (t + (1 << e)) & (TT - 1);
            float2 v = *(const float2*)(g_v + base + (size_t)tv*DD + h*HD + d0);
            o0 += a * v.x; o1 += a * v.y;
        }
        *(float2*)(g_ao + base + (size_t)t*DD + h*HD + d0) = make_float2(o0, o1);
    }
}

// ---------------- launcher ----------------
extern "C" void kernel_launch(void* const* d_in, const int* in_sizes, int n_in,
                              void* d_out, int out_size) {
    const float* x   = (const float*)d_in[0];
    const float* q_w = (const float*)d_in[1];
    const float* q_b = (const float*)d_in[2];
    const float* k_w = (const float*)d_in[3];
    const float* k_b = (const float*)d_in[4];
    const float* v_w = (const float*)d_in[5];
    const float* v_b = (const float*)d_in[6];
    const float* p_w = (const float*)d_in[7];
    const float* p_b = (const float*)d_in[8];
    float* out = (float*)d_out;

    float *pq, *pk, *pv, *pao;
    cudaGetSymbolAddress((void**)&pq,  g_q);
    cudaGetSymbolAddress((void**)&pk,  g_k);
    cudaGetSymbolAddress((void**)&pv,  g_v);
    cudaGetSymbolAddress((void**)&pao, g_ao);

    // 1) transpose x -> g_xt
    transpose_kernel<<<dim3(TT/32, DD/32, BB), dim3(32, 8)>>>(x);
    // 2) convs -> q, k
    conv_kernel<<<dim3(MM/128, DD/128), 256>>>(q_w, q_b, pq);
    conv_kernel<<<dim3(MM/128, DD/128), 256>>>(k_w, k_b, pk);
    // 3) v = x @ v_w^T + v_b
    sgemm_kernel<<<dim3(MM/128, DD/128), 256>>>(x, v_w, v_b, pv, DD);
    // 4) log-sparse softmax weights
    alpha_kernel<<<BB*HH*EE, 256>>>();
    // 5) combine local + log-sparse attention -> g_ao
    combine_kernel<<<dim3(TT, BB), 128>>>();
    // 6) final projection -> d_out
    sgemm_kernel<<<dim3(MM/128, DD/128), 256>>>(pao, p_w, p_b, out, DD);
}

// round 13
// speedup vs baseline: 2.5311x; 2.5311x over previous
#include <cuda_runtime.h>
#include <cuda_fp16.h>
#include <math.h>
#include <stdint.h>

#define BB 2
#define TT 2048
#define DD 1024
#define HH 16
#define HD 64
#define WW 16
#define EE 8
#define MM (BB*TT)          // 4096
#define KCONV (DD*WW)       // 16384

typedef unsigned int u32;
typedef unsigned long long u64;

// ---------------- scratch (device globals; no allocation allowed) ----------------
__device__ __half g_xth[(size_t)BB*DD*TT];   // x hi, layout (b, d, t)
__device__ __half g_xtl[(size_t)BB*DD*TT];   // x lo, layout (b, d, t)
__device__ __half g_xh [(size_t)MM*DD];      // x hi, row-major (m, d)
__device__ __half g_xl [(size_t)MM*DD];
__device__ __half g_wq [(size_t)DD*KCONV];   // q_w fp16 (hi only) [o][i*16+w]
__device__ __half g_wk [(size_t)DD*KCONV];
__device__ __half g_vw [(size_t)DD*DD];
__device__ __half g_pw [(size_t)DD*DD];
__device__ float  g_q  [(size_t)MM*DD];
__device__ float  g_k  [(size_t)MM*DD];
__device__ float  g_v  [(size_t)MM*DD];
__device__ __half g_aoh[(size_t)MM*DD];      // attention out hi
__device__ __half g_aol[(size_t)MM*DD];      // attention out lo
__device__ float  g_alpha[(size_t)BB*HH*EE*TT];

// ---------------- helpers ----------------
__device__ __forceinline__ u32 prmt(u32 a, u32 b, u32 s) {
    u32 d; asm("prmt.b32 %0, %1, %2, %3;" : "=r"(d) : "r"(a), "r"(b), "r"(s)); return d;
}
__device__ __forceinline__ u32 smem_u32(const void* p) {
    u32 a;
    asm("{ .reg .u64 t; cvta.to.shared.u64 t, %1; cvt.u32.u64 %0, t; }" : "=r"(a) : "l"(p));
    return a;
}
__device__ __forceinline__ void cpa16(u32 dst, const void* src) {
    asm volatile("cp.async.cg.shared.global [%0], [%1], 16;" :: "r"(dst), "l"(src));
}
__device__ __forceinline__ void cpa_commit() {
    asm volatile("cp.async.commit_group;" ::: "memory");
}
__device__ __forceinline__ void cpa_wait0() {
    asm volatile("cp.async.wait_group 0;" ::: "memory");
}
__device__ __forceinline__ void ldsm4(u32* r, u32 addr) {
    asm volatile("ldmatrix.sync.aligned.m8n8.x4.shared.b16 {%0,%1,%2,%3}, [%4];"
                 : "=r"(r[0]), "=r"(r[1]), "=r"(r[2]), "=r"(r[3]) : "r"(addr));
}
__device__ __forceinline__ void mma16816(float* c, const u32* a, const u32* b) {
    asm volatile(
        "mma.sync.aligned.m16n8k16.row.col.f32.f16.f16.f32 "
        "{%0,%1,%2,%3}, {%4,%5,%6,%7}, {%8,%9}, {%0,%1,%2,%3};"
        : "+f"(c[0]), "+f"(c[1]), "+f"(c[2]), "+f"(c[3])
        : "r"(a[0]), "r"(a[1]), "r"(a[2]), "r"(a[3]), "r"(b[0]), "r"(b[1]));
}

// ---------------- pack kernels ----------------
// float -> (hi fp16, lo fp16) split arrays
__global__ void split_pack(const float4* __restrict__ in, uint2* __restrict__ hi,
                           uint2* __restrict__ lo, int n4) {
    int i = blockIdx.x * 256 + threadIdx.x;
    if (i >= n4) return;
    float4 v = in[i];
    __half h0 = __float2half_rn(v.x), h1 = __float2half_rn(v.y);
    __half h2 = __float2half_rn(v.z), h3 = __float2half_rn(v.w);
    __half l0 = __float2half_rn(v.x - __half2float(h0));
    __half l1 = __float2half_rn(v.y - __half2float(h1));
    __half l2 = __float2half_rn(v.z - __half2float(h2));
    __half l3 = __float2half_rn(v.w - __half2float(h3));
    uint2 ph, pl;
    ph.x = ((u32)__half_as_ushort(h1) << 16) | __half_as_ushort(h0);
    ph.y = ((u32)__half_as_ushort(h3) << 16) | __half_as_ushort(h2);
    pl.x = ((u32)__half_as_ushort(l1) << 16) | __half_as_ushort(l0);
    pl.y = ((u32)__half_as_ushort(l3) << 16) | __half_as_ushort(l2);
    hi[i] = ph; lo[i] = pl;
}

// float -> hi fp16 only (weights; lo never used)
__global__ void pack_hi(const float4* __restrict__ in, uint2* __restrict__ hi, int n4) {
    int i = blockIdx.x * 256 + threadIdx.x;
    if (i >= n4) return;
    float4 v = in[i];
    __half h0 = __float2half_rn(v.x), h1 = __float2half_rn(v.y);
    __half h2 = __float2half_rn(v.z), h3 = __float2half_rn(v.w);
    uint2 ph;
    ph.x = ((u32)__half_as_ushort(h1) << 16) | __half_as_ushort(h0);
    ph.y = ((u32)__half_as_ushort(h3) << 16) | __half_as_ushort(h2);
    hi[i] = ph;
}

// x (B,T,D) -> xth/xtl (B,D,T) hi/lo halves
__global__ void transpose_split(const float* __restrict__ x) {
    __shared__ float tile[32][33];
    int b  = blockIdx.z;
    int t0 = blockIdx.x * 32, d0 = blockIdx.y * 32;
    int tx = threadIdx.x, ty = threadIdx.y;   // (32, 8)
    #pragma unroll
    for (int j = 0; j < 32; j += 8)
        tile[ty + j][tx] = x[((size_t)b*TT + t0 + ty + j)*DD + d0 + tx];
    __syncthreads();
    #pragma unroll
    for (int j = 0; j < 32; j += 8) {
        float v = tile[tx][ty + j];
        __half h = __float2half_rn(v);
        __half l = __float2half_rn(v - __half2float(h));
        size_t idx = ((size_t)b*DD + d0 + ty + j)*TT + t0 + tx;
        g_xth[idx] = h;
        g_xtl[idx] = l;
    }
}

// ---------------- fused GEMM / implicit-conv kernel (mma.sync fp16, A hi/lo split) --
// C[m,n] = sum_k A[m,k]*B[n,k] + bias[n].  CTA tile 128x128, BK=64 halves, 8 warps.
// Stage layout (bytes): [Ah 0,18432) [Al 18432,36864) [B 36864,55296) [win 55296,+2432)
#define PITCHB 144
#define STAGE  58368
#define WIN_OFF 55296
#define SMEMB  (1024 + 2*STAGE)

template<bool CONV>
__global__ __launch_bounds__(256, 1)
void gemm_kernel(const __half* __restrict__ Ah, const __half* __restrict__ Al,
                 const __half* __restrict__ Bw0, const __half* __restrict__ Bw1,
                 const float* __restrict__ bias0, const float* __restrict__ bias1,
                 float* __restrict__ out0, float* __restrict__ out1, int K)
{
    extern __shared__ __align__(1024) char smem[];
    const int tid  = threadIdx.x;
    const int lane = tid & 31, warp = tid >> 5;
    const int wm = warp >> 2, wn = warp & 3;
    const int m0 = blockIdx.x * 128;
    const int n0 = blockIdx.y * 128;
    const int NC = K >> 6;
    const int bb = m0 >> 11, t0m = m0 & (TT - 1);   // conv only

    const __half* Bw   = (CONV && blockIdx.z) ? Bw1   : Bw0;
    const float*  bias = (CONV && blockIdx.z) ? bias1 : bias0;
    float*        out  = (CONV && blockIdx.z) ? out1  : out0;

    float* sbias = (float*)smem;
    char*  stg0  = smem + 1024;
    const u32 tbase = smem_u32(smem) + 1024;

    if (tid < 128) sbias[tid] = bias[n0 + tid];

    float acc[64];
    #pragma unroll
    for (int i = 0; i < 64; i++) acc[i] = 0.f;

    // ---- producer: issue cp.async for chunk into stage s
    auto issue = [&](int chunk, int s) {
        const u32 stg = tbase + s * STAGE;
        const int k0 = chunk * 64;
        // B tile: 128 rows x 8 chunks of 16B
        for (int t = tid; t < 1024; t += 256) {
            int r = t >> 3, ch = t & 7;
            cpa16(stg + 36864 + r*PITCHB + ch*16,
                  Bw + (size_t)(n0 + r)*K + k0 + ch*8);
        }
        if (CONV) {
            // sliding windows: 4 channels x {hi,lo} x 18 chunks of 8 halves (144 each)
            const int c0 = chunk * 4;
            for (int t = tid; t < 144; t += 256) {
                int idx = t / 18, ch = t % 18;
                int c = idx >> 1, hl = idx & 1;
                int tg = t0m - 16 + ch*8;               // chunk fully valid or fully <0
                u32 dst = stg + WIN_OFF + idx*304 + ch*16;
                if (tg >= 0) {
                    const __half* src = (hl ? Al : Ah) + ((size_t)(bb*DD + c0 + c))*TT + tg;
                    cpa16(dst, src);
                } else {
                    *(uint4*)(stg0 + (dst - tbase)) = make_uint4(0,0,0,0);
                }
            }
        } else {
            for (int t = tid; t < 2048; t += 256) {
                int arr = t >> 10, r = (t >> 3) & 127, ch = t & 7;
                const __half* src = (arr ? Al : Ah) + (size_t)(m0 + r)*K + k0 + ch*8;
                cpa16(stg + arr*18432 + r*PITCHB + ch*16, src);
            }
        }
        cpa_commit();
    };

    // ---- conv: expand windows -> A tiles (hi and lo) in stage s
    auto expand = [&](int s) {
        char* stgc = stg0 + (size_t)s * STAGE;
        for (int t = tid; t < 2048; t += 256) {
            int r = t >> 4;
            int sub = t & 15;
            int c = sub >> 2, hl = (sub >> 1) & 1, w0 = (sub & 1) * 8;
            const u32* win = (const u32*)(stgc + WIN_OFF) + (c*2 + hl)*76;
            int sA = r + 1 + w0;                 // A[r][c*16+w0+j] = win half [sA + j]
            int j0 = sA >> 1;
            uint4 v;
            if (sA & 1) {
                u32 e0 = win[j0], e1 = win[j0+1], e2 = win[j0+2],
                    e3 = win[j0+3], e4 = win[j0+4];
                v = make_uint4(prmt(e0,e1,0x5432), prmt(e1,e2,0x5432),
                               prmt(e2,e3,0x5432), prmt(e3,e4,0x5432));
            } else {
                v = make_uint4(win[j0], win[j0+1], win[j0+2], win[j0+3]);
            }
            *(uint4*)(stgc + hl*18432 + r*PITCHB + c*32 + w0*2) = v;
        }
    };

    // ---- consumer: 4 k16-steps of mma over stage s
    const u32 aoff = (lane & 15)*PITCHB + (lane >> 4)*16;
    const u32 boff = ((lane & 7) + ((lane >> 4) << 3))*PITCHB + ((lane >> 3) & 1)*16;
    auto compute = [&](int s) {
        const u32 stg = tbase + s * STAGE;
        const u32 aH = stg + wm*9216 + aoff;            // wm*64*144
        const u32 aL = aH + 18432;
        const u32 bA = stg + 36864 + wn*4608 + boff;    // wn*32*144
        #pragma unroll
        for (int ks = 0; ks < 4; ks++) {
            u32 ah[4][4], al[4][4], bf[4][2];
            #pragma unroll
            for (int fm = 0; fm < 4; fm++) ldsm4(ah[fm], aH + fm*2304 + ks*32);
            #pragma unroll
            for (int fm = 0; fm < 4; fm++) ldsm4(al[fm], aL + fm*2304 + ks*32);
            { u32 r[4]; ldsm4(r, bA + ks*32);            // n rows 0-15
              bf[0][0]=r[0]; bf[0][1]=r[1]; bf[1][0]=r[2]; bf[1][1]=r[3]; }
            { u32 r[4]; ldsm4(r, bA + 2304 + ks*32);     // n rows 16-31
              bf[2][0]=r[0]; bf[2][1]=r[1]; bf[3][0]=r[2]; bf[3][1]=r[3]; }
            #pragma unroll
            for (int fm = 0; fm < 4; fm++)
                #pragma unroll
                for (int fn = 0; fn < 4; fn++) {
                    mma16816(acc + (fm*4 + fn)*4, ah[fm], bf[fn]);
                    mma16816(acc + (fm*4 + fn)*4, al[fm], bf[fn]);
                }
        }
    };

    // ---- pipelined main loop (2-stage) ----
    issue(0, 0);
    for (int chunk = 0; chunk < NC; chunk++) {
        int s = chunk & 1;
        cpa_wait0();
        __syncthreads();
        if (CONV) expand(s);
        if (chunk + 1 < NC) issue(chunk + 1, 1 - s);
        if (CONV) __syncthreads();
        compute(s);
        if (chunk + 1 < NC) __syncthreads();
    }

    // ---- epilogue ----
    __syncthreads();
    const int g = lane >> 2, tg = lane & 3;
    #pragma unroll
    for (int fm = 0; fm < 4; fm++) {
        int r0 = m0 + wm*64 + fm*16 + g;
        float* p0 = out + (size_t)r0*DD + n0 + wn*32;
        float* p1 = p0 + (size_t)8*DD;
        #pragma unroll
        for (int fn = 0; fn < 4; fn++) {
            const float* a = acc + (fm*4 + fn)*4;
            int cb = wn*32 + fn*8 + tg*2;
            *(float2*)(p0 + fn*8 + tg*2) = make_float2(a[0] + sbias[cb], a[1] + sbias[cb+1]);
            *(float2*)(p1 + fn*8 + tg*2) = make_float2(a[2] + sbias[cb], a[3] + sbias[cb+1]);
        }
    }
}

// ---------------- log-sparse global softmax alpha[b,h,e,t] ----------------
__global__ void alpha_kernel() {
    const int idx = blockIdx.x;                 // (b*H + h)*E + e
    const int e = idx & 7;
    const int h = (idx >> 3) & 15;
    const int b = idx >> 7;
    const int sh = 1 << e;
    const float* qb = g_q + (size_t)b*TT*DD + h*HD;
    const float* kb = g_k + (size_t)b*TT*DD + h*HD;
    const int tid = threadIdx.x;

    float s[8];
    float mx = -1e30f;
    #pragma unroll
    for (int j = 0; j < 8; ++j) {
        int t  = tid + j*256;
        int tk = (t + sh) & (TT - 1);
        const float4* qp = (const float4*)(qb + (size_t)t *DD);
        const float4* kp = (const float4*)(kb + (size_t)tk*DD);
        float a = 0.f;
        #pragma unroll
        for (int d = 0; d < 16; ++d) {
            float4 x = qp[d], y = kp[d];
            a += x.x*y.x + x.y*y.y + x.z*y.z + x.w*y.w;
        }
        s[j] = a * 0.125f;
        mx = fmaxf(mx, s[j]);
    }
    __shared__ float red[256];
    red[tid] = mx; __syncthreads();
    for (int st = 128; st > 0; st >>= 1) {
        if (tid < st) red[tid] = fmaxf(red[tid], red[tid + st]);
        __syncthreads();
    }
    mx = red[0]; __syncthreads();
    float sum = 0.f;
    #pragma unroll
    for (int j = 0; j < 8; ++j) { s[j] = expf(s[j] - mx); sum += s[j]; }
    red[tid] = sum; __syncthreads();
    for (int st = 128; st > 0; st >>= 1) {
        if (tid < st) red[tid] += red[tid + st];
        __syncthreads();
    }
    const float inv = 1.f / red[0];
    float* ab = g_alpha + (size_t)idx * TT;
    #pragma unroll
    for (int j = 0; j < 8; ++j) ab[tid + j*256] = s[j] * inv;
}

// ---------------- local window attention + log-sparse combine --------------------
__global__ void combine_kernel() {
    const int t = blockIdx.x, b = blockIdx.y;
    const int warp = threadIdx.x >> 5, lane = threadIdx.x & 31;
    const size_t base = (size_t)b*TT*DD;

    for (int h = warp; h < HH; h += 4) {
        const float* qp = g_q + base + (size_t)t*DD + h*HD;
        float sc = 0.f;
        if (lane < 16) {
            int tk = t - 15 + lane;
            if (tk >= 0) {
                const float4* q4 = (const float4*)qp;
                const float4* k4 = (const float4*)(g_k + base + (size_t)tk*DD + h*HD);
                float a = 0.f;
                #pragma unroll
                for (int d = 0; d < 16; ++d) {
                    float4 x = q4[d], y = k4[d];
                    a += x.x*y.x + x.y*y.y + x.z*y.z + x.w*y.w;
                }
                sc = a * 0.125f;
            }
        }
        float m = sc;
        #pragma unroll
        for (int o = 8; o; o >>= 1) m = fmaxf(m, __shfl_xor_sync(0xffffffffu, m, o, 16));
        float p = expf(sc - m);
        float ss = p;
        #pragma unroll
        for (int o = 8; o; o >>= 1) ss += __shfl_xor_sync(0xffffffffu, ss, o, 16);
        float pn = p / ss;

        const int d0 = lane * 2;
        float o0 = 0.f, o1 = 0.f;
        #pragma unroll
        for (int j = 0; j < 16; ++j) {
            float pj = __shfl_sync(0xffffffffu, pn, j);
            int tk = t - 15 + j;
            if (tk >= 0) {
                float2 v = *(const float2*)(g_v + base + (size_t)tk*DD + h*HD + d0);
                o0 += pj * v.x; o1 += pj * v.y;
            }
        }
        const float* ab = g_alpha + (size_t)(b*HH + h)*EE*TT;
        #pragma unroll
        for (int e = 0; e < EE; ++e) {
            float a = ab[(size_t)e*TT + t];
            int tv = (t + (1 << e)) & (TT - 1);
            float2 v = *(const float2*)(g_v + base + (size_t)tv*DD + h*HD + d0);
            o0 += a * v.x; o1 += a * v.y;
        }
        __half h0 = __float2half_rn(o0), h1 = __float2half_rn(o1);
        __half l0 = __float2half_rn(o0 - __half2float(h0));
        __half l1 = __float2half_rn(o1 - __half2float(h1));
        size_t oidx = base + (size_t)t*DD + h*HD + d0;
        *(__half2*)(g_aoh + oidx) = __halves2half2(h0, h1);
        *(__half2*)(g_aol + oidx) = __halves2half2(l0, l1);
    }
}

// ---------------- launcher ----------------
extern "C" void kernel_launch(void* const* d_in, const int* in_sizes, int n_in,
                              void* d_out, int out_size) {
    const float* x   = (const float*)d_in[0];
    const float* q_w = (const float*)d_in[1];
    const float* q_b = (const float*)d_in[2];
    const float* k_w = (const float*)d_in[3];
    const float* k_b = (const float*)d_in[4];
    const float* v_w = (const float*)d_in[5];
    const float* v_b = (const float*)d_in[6];
    const float* p_w = (const float*)d_in[7];
    const float* p_b = (const float*)d_in[8];
    float* out = (float*)d_out;

    __half *pxth, *pxtl, *pxh, *pxl, *pwq, *pwk, *pvw, *ppw, *paoh, *paol;
    float *pq, *pk, *pv;
    cudaGetSymbolAddress((void**)&pxth, g_xth);
    cudaGetSymbolAddress((void**)&pxtl, g_xtl);
    cudaGetSymbolAddress((void**)&pxh,  g_xh);
    cudaGetSymbolAddress((void**)&pxl,  g_xl);
    cudaGetSymbolAddress((void**)&pwq,  g_wq);
    cudaGetSymbolAddress((void**)&pwk,  g_wk);
    cudaGetSymbolAddress((void**)&pvw,  g_vw);
    cudaGetSymbolAddress((void**)&ppw,  g_pw);
    cudaGetSymbolAddress((void**)&paoh, g_aoh);
    cudaGetSymbolAddress((void**)&paol, g_aol);
    cudaGetSymbolAddress((void**)&pq,   g_q);
    cudaGetSymbolAddress((void**)&pk,   g_k);
    cudaGetSymbolAddress((void**)&pv,   g_v);

    cudaFuncSetAttribute(gemm_kernel<true>,  cudaFuncAttributeMaxDynamicSharedMemorySize, SMEMB);
    cudaFuncSetAttribute(gemm_kernel<false>, cudaFuncAttributeMaxDynamicSharedMemorySize, SMEMB);

    // 1) pack inputs
    transpose_split<<<dim3(TT/32, DD/32, BB), dim3(32, 8)>>>(x);
    split_pack<<<(MM*DD/4 + 255)/256, 256>>>((const float4*)x, (uint2*)pxh, (uint2*)pxl, MM*DD/4);
    {
        int n4 = DD*KCONV/4;
        pack_hi<<<(n4 + 255)/256, 256>>>((const float4*)q_w, (uint2*)pwq, n4);
        pack_hi<<<(n4 + 255)/256, 256>>>((const float4*)k_w, (uint2*)pwk, n4);
    }
    {
        int n4 = DD*DD/4;
        pack_hi<<<(n4 + 255)/256, 256>>>((const float4*)v_w, (uint2*)pvw, n4);
        pack_hi<<<(n4 + 255)/256, 256>>>((const float4*)p_w, (uint2*)ppw, n4);
    }

    // 2) both convs in one launch -> q, k
    gemm_kernel<true><<<dim3(MM/128, DD/128, 2), 256, SMEMB>>>(
        pxth, pxtl, pwq, pwk, q_b, k_b, pq, pk, KCONV);
    // 3) v = x @ v_w^T + v_b
    gemm_kernel<false><<<dim3(MM/128, DD/128, 1), 256, SMEMB>>>(
        pxh, pxl, pvw, pvw, v_b, v_b, pv, pv, DD);
    // 4) log-sparse softmax weights
    alpha_kernel<<<BB*HH*EE, 256>>>();
    // 5) combine local + log-sparse attention -> aoh/aol
    combine_kernel<<<dim3(TT, BB), 128>>>();
    // 6) final projection -> d_out
    gemm_kernel<false><<<dim3(MM/128, DD/128, 1), 256, SMEMB>>>(
        paoh, paol, ppw, ppw, p_b, p_b, out, out, DD);
}

// round 14
// speedup vs baseline: 2.6033x; 1.0285x over previous
#include <cuda_runtime.h>
#include <cuda_fp16.h>
#include <math.h>
#include <stdint.h>

#define BB 2
#define TT 2048
#define DD 1024
#define HH 16
#define HD 64
#define WW 16
#define EE 8
#define MM (BB*TT)          // 4096
#define KCONV (DD*WW)       // 16384

typedef unsigned int u32;
typedef unsigned long long u64;

// ---------------- scratch (device globals; no allocation allowed) ----------------
__device__ __half g_xth[(size_t)BB*DD*TT];   // x hi, layout (b, d, t)
__device__ __half g_xtl[(size_t)BB*DD*TT];   // x lo, layout (b, d, t)
__device__ __half g_xh [(size_t)MM*DD];      // x hi, row-major (m, d)
__device__ __half g_xl [(size_t)MM*DD];
__device__ __half g_wq [(size_t)DD*KCONV];   // q_w fp16 (hi only) [o][i*16+w]
__device__ __half g_wk [(size_t)DD*KCONV];
__device__ __half g_vw [(size_t)DD*DD];
__device__ __half g_pw [(size_t)DD*DD];
__device__ float  g_q  [(size_t)MM*DD];
__device__ float  g_k  [(size_t)MM*DD];
__device__ float  g_v  [(size_t)MM*DD];
__device__ __half g_aoh[(size_t)MM*DD];      // attention out hi
__device__ __half g_aol[(size_t)MM*DD];      // attention out lo
__device__ float  g_alpha[(size_t)BB*HH*EE*TT];

// ---------------- helpers ----------------
__device__ __forceinline__ u32 prmt(u32 a, u32 b, u32 s) {
    u32 d; asm("prmt.b32 %0, %1, %2, %3;" : "=r"(d) : "r"(a), "r"(b), "r"(s)); return d;
}
__device__ __forceinline__ u32 smem_u32(const void* p) {
    u32 a;
    asm("{ .reg .u64 t; cvta.to.shared.u64 t, %1; cvt.u32.u64 %0, t; }" : "=r"(a) : "l"(p));
    return a;
}
__device__ __forceinline__ void cpa16(u32 dst, const void* src) {
    asm volatile("cp.async.cg.shared.global [%0], [%1], 16;" :: "r"(dst), "l"(src));
}
__device__ __forceinline__ void cpa_commit() {
    asm volatile("cp.async.commit_group;" ::: "memory");
}
__device__ __forceinline__ void cpa_wait0() {
    asm volatile("cp.async.wait_group 0;" ::: "memory");
}
__device__ __forceinline__ void ldsm4(u32* r, u32 addr) {
    asm volatile("ldmatrix.sync.aligned.m8n8.x4.shared.b16 {%0,%1,%2,%3}, [%4];"
                 : "=r"(r[0]), "=r"(r[1]), "=r"(r[2]), "=r"(r[3]) : "r"(addr));
}
__device__ __forceinline__ void mma16816(float* c, const u32* a, const u32* b) {
    asm volatile(
        "mma.sync.aligned.m16n8k16.row.col.f32.f16.f16.f32 "
        "{%0,%1,%2,%3}, {%4,%5,%6,%7}, {%8,%9}, {%0,%1,%2,%3};"
        : "+f"(c[0]), "+f"(c[1]), "+f"(c[2]), "+f"(c[3])
        : "r"(a[0]), "r"(a[1]), "r"(a[2]), "r"(a[3]), "r"(b[0]), "r"(b[1]));
}

// ---------------- pack kernels ----------------
// float -> (hi fp16, lo fp16) split arrays
__global__ void split_pack(const float4* __restrict__ in, uint2* __restrict__ hi,
                           uint2* __restrict__ lo, int n4) {
    int i = blockIdx.x * 256 + threadIdx.x;
    if (i >= n4) return;
    float4 v = in[i];
    __half h0 = __float2half_rn(v.x), h1 = __float2half_rn(v.y);
    __half h2 = __float2half_rn(v.z), h3 = __float2half_rn(v.w);
    __half l0 = __float2half_rn(v.x - __half2float(h0));
    __half l1 = __float2half_rn(v.y - __half2float(h1));
    __half l2 = __float2half_rn(v.z - __half2float(h2));
    __half l3 = __float2half_rn(v.w - __half2float(h3));
    uint2 ph, pl;
    ph.x = ((u32)__half_as_ushort(h1) << 16) | __half_as_ushort(h0);
    ph.y = ((u32)__half_as_ushort(h3) << 16) | __half_as_ushort(h2);
    pl.x = ((u32)__half_as_ushort(l1) << 16) | __half_as_ushort(l0);
    pl.y = ((u32)__half_as_ushort(l3) << 16) | __half_as_ushort(l2);
    hi[i] = ph; lo[i] = pl;
}

// float -> hi fp16 only (weights; lo never used)
__global__ void pack_hi(const float4* __restrict__ in, uint2* __restrict__ hi, int n4) {
    int i = blockIdx.x * 256 + threadIdx.x;
    if (i >= n4) return;
    float4 v = in[i];
    __half h0 = __float2half_rn(v.x), h1 = __float2half_rn(v.y);
    __half h2 = __float2half_rn(v.z), h3 = __float2half_rn(v.w);
    uint2 ph;
    ph.x = ((u32)__half_as_ushort(h1) << 16) | __half_as_ushort(h0);
    ph.y = ((u32)__half_as_ushort(h3) << 16) | __half_as_ushort(h2);
    hi[i] = ph;
}

// two arrays in one launch (keeps QKV GEMM at ncu launch index 5)
__global__ void pack_hi2(const float4* __restrict__ inA, const float4* __restrict__ inB,
                         uint2* __restrict__ dstA, uint2* __restrict__ dstB, int n4) {
    int i = blockIdx.x * 256 + threadIdx.x;
    if (i >= n4) return;
    const float4* in = blockIdx.y ? inB : inA;
    uint2* dst = blockIdx.y ? dstB : dstA;
    float4 v = in[i];
    __half h0 = __float2half_rn(v.x), h1 = __float2half_rn(v.y);
    __half h2 = __float2half_rn(v.z), h3 = __float2half_rn(v.w);
    uint2 ph;
    ph.x = ((u32)__half_as_ushort(h1) << 16) | __half_as_ushort(h0);
    ph.y = ((u32)__half_as_ushort(h3) << 16) | __half_as_ushort(h2);
    dst[i] = ph;
}

// x (B,T,D) -> xth/xtl (B,D,T) hi/lo halves
__global__ void transpose_split(const float* __restrict__ x) {
    __shared__ float tile[32][33];
    int b  = blockIdx.z;
    int t0 = blockIdx.x * 32, d0 = blockIdx.y * 32;
    int tx = threadIdx.x, ty = threadIdx.y;   // (32, 8)
    #pragma unroll
    for (int j = 0; j < 32; j += 8)
        tile[ty + j][tx] = x[((size_t)b*TT + t0 + ty + j)*DD + d0 + tx];
    __syncthreads();
    #pragma unroll
    for (int j = 0; j < 32; j += 8) {
        float v = tile[tx][ty + j];
        __half h = __float2half_rn(v);
        __half l = __float2half_rn(v - __half2float(h));
        size_t idx = ((size_t)b*DD + d0 + ty + j)*TT + t0 + tx;
        g_xth[idx] = h;
        g_xtl[idx] = l;
    }
}

// ---------------- shared GEMM machinery (mma.sync fp16, A hi/lo split) ----------
// C[m,n] = sum_k A[m,k]*B[n,k] + bias[n].  CTA tile 128x128, BK=64 halves, 8 warps.
// Stage layout (bytes): [Ah 0,18432) [Al 18432,36864) [B 36864,55296) [win 55296,+2432)
#define PITCHB 144
#define STAGE  58368
#define WIN_OFF 55296
#define SMEMB  (1024 + 2*STAGE)

// ---------------- fused QKV kernel: z=0 q-conv, z=1 k-conv, z=2 v-gemm ----------
__global__ __launch_bounds__(256, 1)
void qkv_kernel(const __half* __restrict__ xth, const __half* __restrict__ xtl,
                const __half* __restrict__ xh,  const __half* __restrict__ xl,
                const __half* __restrict__ wq,  const __half* __restrict__ wk,
                const __half* __restrict__ vw,
                const float* __restrict__ qb, const float* __restrict__ kb,
                const float* __restrict__ vb,
                float* __restrict__ outq, float* __restrict__ outk,
                float* __restrict__ outv)
{
    extern __shared__ __align__(1024) char smem[];
    const int tid  = threadIdx.x;
    const int lane = tid & 31, warp = tid >> 5;
    const int wm = warp >> 2, wn = warp & 3;
    const int m0 = blockIdx.x * 128;
    const int n0 = blockIdx.y * 128;
    const int z  = blockIdx.z;
    const bool conv = (z < 2);
    const int K  = conv ? KCONV : DD;
    const int NC = K >> 6;
    const int bb = m0 >> 11, t0m = m0 & (TT - 1);

    const __half* Bw   = (z == 0) ? wq : (z == 1) ? wk : vw;
    const float*  bias = (z == 0) ? qb : (z == 1) ? kb : vb;
    float*        out  = (z == 0) ? outq : (z == 1) ? outk : outv;

    float* sbias = (float*)smem;
    char*  stg0  = smem + 1024;
    const u32 tbase = smem_u32(smem) + 1024;

    if (tid < 128) sbias[tid] = bias[n0 + tid];

    float acc[64];
    #pragma unroll
    for (int i = 0; i < 64; i++) acc[i] = 0.f;

    auto issue = [&](int chunk, int s) {
        const u32 stg = tbase + s * STAGE;
        const int k0 = chunk * 64;
        for (int t = tid; t < 1024; t += 256) {
            int r = t >> 3, ch = t & 7;
            cpa16(stg + 36864 + r*PITCHB + ch*16,
                  Bw + (size_t)(n0 + r)*K + k0 + ch*8);
        }
        if (conv) {
            const int c0 = chunk * 4;
            for (int t = tid; t < 144; t += 256) {
                int idx = t / 18, ch = t % 18;
                int c = idx >> 1, hl = idx & 1;
                int tg = t0m - 16 + ch*8;               // chunk fully valid or fully <0
                u32 dst = stg + WIN_OFF + idx*304 + ch*16;
                if (tg >= 0) {
                    const __half* src = (hl ? xtl : xth) + ((size_t)(bb*DD + c0 + c))*TT + tg;
                    cpa16(dst, src);
                } else {
                    *(uint4*)(stg0 + (dst - tbase)) = make_uint4(0,0,0,0);
                }
            }
        } else {
            for (int t = tid; t < 2048; t += 256) {
                int arr = t >> 10, r = (t >> 3) & 127, ch = t & 7;
                const __half* src = (arr ? xl : xh) + (size_t)(m0 + r)*K + k0 + ch*8;
                cpa16(stg + arr*18432 + r*PITCHB + ch*16, src);
            }
        }
        cpa_commit();
    };

    auto expand = [&](int s) {
        char* stgc = stg0 + (size_t)s * STAGE;
        for (int t = tid; t < 2048; t += 256) {
            int r = t >> 4;
            int sub = t & 15;
            int c = sub >> 2, hl = (sub >> 1) & 1, w0 = (sub & 1) * 8;
            const u32* win = (const u32*)(stgc + WIN_OFF) + (c*2 + hl)*76;
            int sA = r + 1 + w0;                 // A[r][c*16+w0+j] = win half [sA + j]
            int j0 = sA >> 1;
            uint4 v;
            if (sA & 1) {
                u32 e0 = win[j0], e1 = win[j0+1], e2 = win[j0+2],
                    e3 = win[j0+3], e4 = win[j0+4];
                v = make_uint4(prmt(e0,e1,0x5432), prmt(e1,e2,0x5432),
                               prmt(e2,e3,0x5432), prmt(e3,e4,0x5432));
            } else {
                v = make_uint4(win[j0], win[j0+1], win[j0+2], win[j0+3]);
            }
            *(uint4*)(stgc + hl*18432 + r*PITCHB + c*32 + w0*2) = v;
        }
    };

    const u32 aoff = (lane & 15)*PITCHB + (lane >> 4)*16;
    const u32 boff = ((lane & 7) + ((lane >> 4) << 3))*PITCHB + ((lane >> 3) & 1)*16;
    auto compute = [&](int s) {
        const u32 stg = tbase + s * STAGE;
        const u32 aH = stg + wm*9216 + aoff;            // wm*64*144
        const u32 aL = aH + 18432;
        const u32 bA = stg + 36864 + wn*4608 + boff;    // wn*32*144
        #pragma unroll
        for (int ks = 0; ks < 4; ks++) {
            u32 ah[4][4], al[4][4], bf[4][2];
            #pragma unroll
            for (int fm = 0; fm < 4; fm++) ldsm4(ah[fm], aH + fm*2304 + ks*32);
            #pragma unroll
            for (int fm = 0; fm < 4; fm++) ldsm4(al[fm], aL + fm*2304 + ks*32);
            { u32 r[4]; ldsm4(r, bA + ks*32);            // n rows 0-15
              bf[0][0]=r[0]; bf[0][1]=r[1]; bf[1][0]=r[2]; bf[1][1]=r[3]; }
            { u32 r[4]; ldsm4(r, bA + 2304 + ks*32);     // n rows 16-31
              bf[2][0]=r[0]; bf[2][1]=r[1]; bf[3][0]=r[2]; bf[3][1]=r[3]; }
            #pragma unroll
            for (int fm = 0; fm < 4; fm++)
                #pragma unroll
                for (int fn = 0; fn < 4; fn++) {
                    mma16816(acc + (fm*4 + fn)*4, ah[fm], bf[fn]);
                    mma16816(acc + (fm*4 + fn)*4, al[fm], bf[fn]);
                }
        }
    };

    issue(0, 0);
    for (int chunk = 0; chunk < NC; chunk++) {
        int s = chunk & 1;
        cpa_wait0();
        __syncthreads();
        if (conv) expand(s);
        if (chunk + 1 < NC) issue(chunk + 1, 1 - s);
        if (conv) __syncthreads();
        compute(s);
        if (chunk + 1 < NC) __syncthreads();
    }

    __syncthreads();
    const int g = lane >> 2, tg = lane & 3;
    #pragma unroll
    for (int fm = 0; fm < 4; fm++) {
        int r0 = m0 + wm*64 + fm*16 + g;
        float* p0 = out + (size_t)r0*DD + n0 + wn*32;
        float* p1 = p0 + (size_t)8*DD;
        #pragma unroll
        for (int fn = 0; fn < 4; fn++) {
            const float* a = acc + (fm*4 + fn)*4;
            int cb = wn*32 + fn*8 + tg*2;
            *(float2*)(p0 + fn*8 + tg*2) = make_float2(a[0] + sbias[cb], a[1] + sbias[cb+1]);
            *(float2*)(p1 + fn*8 + tg*2) = make_float2(a[2] + sbias[cb], a[3] + sbias[cb+1]);
        }
    }
}

// ---------------- plain GEMM kernel (p projection) ------------------------------
__global__ __launch_bounds__(256, 1)
void gemm_kernel(const __half* __restrict__ Ah, const __half* __restrict__ Al,
                 const __half* __restrict__ Bw,
                 const float* __restrict__ bias,
                 float* __restrict__ out, int K)
{
    extern __shared__ __align__(1024) char smem[];
    const int tid  = threadIdx.x;
    const int lane = tid & 31, warp = tid >> 5;
    const int wm = warp >> 2, wn = warp & 3;
    const int m0 = blockIdx.x * 128;
    const int n0 = blockIdx.y * 128;
    const int NC = K >> 6;

    float* sbias = (float*)smem;
    const u32 tbase = smem_u32(smem) + 1024;

    if (tid < 128) sbias[tid] = bias[n0 + tid];

    float acc[64];
    #pragma unroll
    for (int i = 0; i < 64; i++) acc[i] = 0.f;

    auto issue = [&](int chunk, int s) {
        const u32 stg = tbase + s * STAGE;
        const int k0 = chunk * 64;
        for (int t = tid; t < 1024; t += 256) {
            int r = t >> 3, ch = t & 7;
            cpa16(stg + 36864 + r*PITCHB + ch*16,
                  Bw + (size_t)(n0 + r)*K + k0 + ch*8);
        }
        for (int t = tid; t < 2048; t += 256) {
            int arr = t >> 10, r = (t >> 3) & 127, ch = t & 7;
            const __half* src = (arr ? Al : Ah) + (size_t)(m0 + r)*K + k0 + ch*8;
            cpa16(stg + arr*18432 + r*PITCHB + ch*16, src);
        }
        cpa_commit();
    };

    const u32 aoff = (lane & 15)*PITCHB + (lane >> 4)*16;
    const u32 boff = ((lane & 7) + ((lane >> 4) << 3))*PITCHB + ((lane >> 3) & 1)*16;
    auto compute = [&](int s) {
        const u32 stg = tbase + s * STAGE;
        const u32 aH = stg + wm*9216 + aoff;
        const u32 aL = aH + 18432;
        const u32 bA = stg + 36864 + wn*4608 + boff;
        #pragma unroll
        for (int ks = 0; ks < 4; ks++) {
            u32 ah[4][4], al[4][4], bf[4][2];
            #pragma unroll
            for (int fm = 0; fm < 4; fm++) ldsm4(ah[fm], aH + fm*2304 + ks*32);
            #pragma unroll
            for (int fm = 0; fm < 4; fm++) ldsm4(al[fm], aL + fm*2304 + ks*32);
            { u32 r[4]; ldsm4(r, bA + ks*32);
              bf[0][0]=r[0]; bf[0][1]=r[1]; bf[1][0]=r[2]; bf[1][1]=r[3]; }
            { u32 r[4]; ldsm4(r, bA + 2304 + ks*32);
              bf[2][0]=r[0]; bf[2][1]=r[1]; bf[3][0]=r[2]; bf[3][1]=r[3]; }
            #pragma unroll
            for (int fm = 0; fm < 4; fm++)
                #pragma unroll
                for (int fn = 0; fn < 4; fn++) {
                    mma16816(acc + (fm*4 + fn)*4, ah[fm], bf[fn]);
                    mma16816(acc + (fm*4 + fn)*4, al[fm], bf[fn]);
                }
        }
    };

    issue(0, 0);
    for (int chunk = 0; chunk < NC; chunk++) {
        int s = chunk & 1;
        cpa_wait0();
        __syncthreads();
        if (chunk + 1 < NC) issue(chunk + 1, 1 - s);
        compute(s);
        if (chunk + 1 < NC) __syncthreads();
    }

    __syncthreads();
    const int g = lane >> 2, tg = lane & 3;
    #pragma unroll
    for (int fm = 0; fm < 4; fm++) {
        int r0 = m0 + wm*64 + fm*16 + g;
        float* p0 = out + (size_t)r0*DD + n0 + wn*32;
        float* p1 = p0 + (size_t)8*DD;
        #pragma unroll
        for (int fn = 0; fn < 4; fn++) {
            const float* a = acc + (fm*4 + fn)*4;
            int cb = wn*32 + fn*8 + tg*2;
            *(float2*)(p0 + fn*8 + tg*2) = make_float2(a[0] + sbias[cb], a[1] + sbias[cb+1]);
            *(float2*)(p1 + fn*8 + tg*2) = make_float2(a[2] + sbias[cb], a[3] + sbias[cb+1]);
        }
    }
}

// ---------------- log-sparse global softmax alpha[b,h,e,t] ----------------
__global__ void alpha_kernel() {
    const int idx = blockIdx.x;                 // (b*H + h)*E + e
    const int e = idx & 7;
    const int h = (idx >> 3) & 15;
    const int b = idx >> 7;
    const int sh = 1 << e;
    const float* qb = g_q + (size_t)b*TT*DD + h*HD;
    const float* kb = g_k + (size_t)b*TT*DD + h*HD;
    const int tid = threadIdx.x;

    float s[8];
    float mx = -1e30f;
    #pragma unroll
    for (int j = 0; j < 8; ++j) {
        int t  = tid + j*256;
        int tk = (t + sh) & (TT - 1);
        const float4* qp = (const float4*)(qb + (size_t)t *DD);
        const float4* kp = (const float4*)(kb + (size_t)tk*DD);
        float a = 0.f;
        #pragma unroll
        for (int d = 0; d < 16; ++d) {
            float4 x = qp[d], y = kp[d];
            a += x.x*y.x + x.y*y.y + x.z*y.z + x.w*y.w;
        }
        s[j] = a * 0.125f;
        mx = fmaxf(mx, s[j]);
    }
    __shared__ float red[256];
    red[tid] = mx; __syncthreads();
    for (int st = 128; st > 0; st >>= 1) {
        if (tid < st) red[tid] = fmaxf(red[tid], red[tid + st]);
        __syncthreads();
    }
    mx = red[0]; __syncthreads();
    float sum = 0.f;
    #pragma unroll
    for (int j = 0; j < 8; ++j) { s[j] = expf(s[j] - mx); sum += s[j]; }
    red[tid] = sum; __syncthreads();
    for (int st = 128; st > 0; st >>= 1) {
        if (tid < st) red[tid] += red[tid + st];
        __syncthreads();
    }
    const float inv = 1.f / red[0];
    float* ab = g_alpha + (size_t)idx * TT;
    #pragma unroll
    for (int j = 0; j < 8; ++j) ab[tid + j*256] = s[j] * inv;
}

// ---------------- local window attention + log-sparse combine --------------------
__global__ void combine_kernel() {
    const int t = blockIdx.x, b = blockIdx.y;
    const int warp = threadIdx.x >> 5, lane = threadIdx.x & 31;
    const size_t base = (size_t)b*TT*DD;

    for (int h = warp; h < HH; h += 4) {
        const float* qp = g_q + base + (size_t)t*DD + h*HD;
        float sc = 0.f;
        if (lane < 16) {
            int tk = t - 15 + lane;
            if (tk >= 0) {
                const float4* q4 = (const float4*)qp;
                const float4* k4 = (const float4*)(g_k + base + (size_t)tk*DD + h*HD);
                float a = 0.f;
                #pragma unroll
                for (int d = 0; d < 16; ++d) {
                    float4 x = q4[d], y = k4[d];
                    a += x.x*y.x + x.y*y.y + x.z*y.z + x.w*y.w;
                }
                sc = a * 0.125f;
            }
        }
        float m = sc;
        #pragma unroll
        for (int o = 8; o; o >>= 1) m = fmaxf(m, __shfl_xor_sync(0xffffffffu, m, o, 16));
        float p = expf(sc - m);
        float ss = p;
        #pragma unroll
        for (int o = 8; o; o >>= 1) ss += __shfl_xor_sync(0xffffffffu, ss, o, 16);
        float pn = p / ss;

        const int d0 = lane * 2;
        float o0 = 0.f, o1 = 0.f;
        #pragma unroll
        for (int j = 0; j < 16; ++j) {
            float pj = __shfl_sync(0xffffffffu, pn, j);
            int tk = t - 15 + j;
            if (tk >= 0) {
                float2 v = *(const float2*)(g_v + base + (size_t)tk*DD + h*HD + d0);
                o0 += pj * v.x; o1 += pj * v.y;
            }
        }
        const float* ab = g_alpha + (size_t)(b*HH + h)*EE*TT;
        #pragma unroll
        for (int e = 0; e < EE; ++e) {
            float a = ab[(size_t)e*TT + t];
            int tv = (t + (1 << e)) & (TT - 1);
            float2 v = *(const float2*)(g_v + base + (size_t)tv*DD + h*HD + d0);
            o0 += a * v.x; o1 += a * v.y;
        }
        __half h0 = __float2half_rn(o0), h1 = __float2half_rn(o1);
        __half l0 = __float2half_rn(o0 - __half2float(h0));
        __half l1 = __float2half_rn(o1 - __half2float(h1));
        size_t oidx = base + (size_t)t*DD + h*HD + d0;
        *(__half2*)(g_aoh + oidx) = __halves2half2(h0, h1);
        *(__half2*)(g_aol + oidx) = __halves2half2(l0, l1);
    }
}

// ---------------- launcher ----------------
extern "C" void kernel_launch(void* const* d_in, const int* in_sizes, int n_in,
                              void* d_out, int out_size) {
    const float* x   = (const float*)d_in[0];
    const float* q_w = (const float*)d_in[1];
    const float* q_b = (const float*)d_in[2];
    const float* k_w = (const float*)d_in[3];
    const float* k_b = (const float*)d_in[4];
    const float* v_w = (const float*)d_in[5];
    const float* v_b = (const float*)d_in[6];
    const float* p_w = (const float*)d_in[7];
    const float* p_b = (const float*)d_in[8];
    float* out = (float*)d_out;

    __half *pxth, *pxtl, *pxh, *pxl, *pwq, *pwk, *pvw, *ppw, *paoh, *paol;
    float *pq, *pk, *pv;
    cudaGetSymbolAddress((void**)&pxth, g_xth);
    cudaGetSymbolAddress((void**)&pxtl, g_xtl);
    cudaGetSymbolAddress((void**)&pxh,  g_xh);
    cudaGetSymbolAddress((void**)&pxl,  g_xl);
    cudaGetSymbolAddress((void**)&pwq,  g_wq);
    cudaGetSymbolAddress((void**)&pwk,  g_wk);
    cudaGetSymbolAddress((void**)&pvw,  g_vw);
    cudaGetSymbolAddress((void**)&ppw,  g_pw);
    cudaGetSymbolAddress((void**)&paoh, g_aoh);
    cudaGetSymbolAddress((void**)&paol, g_aol);
    cudaGetSymbolAddress((void**)&pq,   g_q);
    cudaGetSymbolAddress((void**)&pk,   g_k);
    cudaGetSymbolAddress((void**)&pv,   g_v);

    cudaFuncSetAttribute(qkv_kernel,  cudaFuncAttributeMaxDynamicSharedMemorySize, SMEMB);
    cudaFuncSetAttribute(gemm_kernel, cudaFuncAttributeMaxDynamicSharedMemorySize, SMEMB);

    // launch index:                                                         (ncu -s 5)
    // 0: transpose_split   1: split_pack(x)   2: pack_hi(q_w)  3: pack_hi(k_w)
    // 4: pack_hi2(v_w,p_w) 5: qkv_kernel  <-- profiled next round
    transpose_split<<<dim3(TT/32, DD/32, BB), dim3(32, 8)>>>(x);
    split_pack<<<(MM*DD/4 + 255)/256, 256>>>((const float4*)x, (uint2*)pxh, (uint2*)pxl, MM*DD/4);
    {
        int n4 = DD*KCONV/4;
        pack_hi<<<(n4 + 255)/256, 256>>>((const float4*)q_w, (uint2*)pwq, n4);
        pack_hi<<<(n4 + 255)/256, 256>>>((const float4*)k_w, (uint2*)pwk, n4);
    }
    {
        int n4 = DD*DD/4;
        pack_hi2<<<dim3((n4 + 255)/256, 2), 256>>>(
            (const float4*)v_w, (const float4*)p_w, (uint2*)pvw, (uint2*)ppw, n4);
    }

    // fused q-conv / k-conv / v-gemm: light v CTAs (z=2) fill the conv tail wave
    qkv_kernel<<<dim3(MM/128, DD/128, 3), 256, SMEMB>>>(
        pxth, pxtl, pxh, pxl, pwq, pwk, pvw, q_b, k_b, v_b, pq, pk, pv);

    alpha_kernel<<<BB*HH*EE, 256>>>();
    combine_kernel<<<dim3(TT, BB), 128>>>();
    gemm_kernel<<<dim3(MM/128, DD/128, 1), 256, SMEMB>>>(
        paoh, paol, ppw, p_b, out, DD);
}